// round 7
// baseline (speedup 1.0000x reference)
#include <cuda_runtime.h>
#include <cuda_bf16.h>
#include <cuda_fp16.h>
#include <math.h>
#include <stdint.h>

#define NL 4
#define NB 32
#define NH 512
#define NV 32000
#define NTT 51

typedef unsigned long long u64;

// ================= persistent device scratch =================
__device__ u64 g_x[2][NL][16][512];      // layer-input pairs (l>=1), ping-pong by t parity
__device__ u64 g_hb[2][NL][16][512];     // clamped hidden pairs, ping-pong by t parity
__device__ u64 g_c2[NL][16][512];        // clamped cell pairs
__device__ u64 g_emb2[NTT][16][512];     // pre-gathered embedding pairs per timestep
__device__ float g_htop[1664 * NH];      // top-layer hidden per step (pad rows stay 0)

// fp16 operands for the projection: htop split hi/lo, W rounded once
__device__ __half g_Hs[2][1664 * 512];
__device__ __half g_Ws[NV * 512];

// ================= helpers =================
__device__ __forceinline__ u64 pk2(float lo, float hi) {
    u64 r;
    asm("mov.b64 %0, {%1, %2};" : "=l"(r) : "r"(__float_as_uint(lo)), "r"(__float_as_uint(hi)));
    return r;
}
__device__ __forceinline__ void upk2(u64 v, float &lo, float &hi) {
    unsigned a, b;
    asm("mov.b64 {%0, %1}, %2;" : "=r"(a), "=r"(b) : "l"(v));
    lo = __uint_as_float(a); hi = __uint_as_float(b);
}
__device__ __forceinline__ u64 ffma2(u64 a, u64 b, u64 c) {
    u64 d;
    asm("fma.rn.f32x2 %0, %1, %2, %3;" : "=l"(d) : "l"(a), "l"(b), "l"(c));
    return d;
}
__device__ __forceinline__ u64 fadd2(u64 a, u64 b) {
    u64 d;
    asm("add.rn.f32x2 %0, %1, %2;" : "=l"(d) : "l"(a), "l"(b));
    return d;
}
__device__ __forceinline__ float sigmoidf_(float x) { return 1.0f / (1.0f + expf(-x)); }
__device__ __forceinline__ float clip50(float x) { return fminf(fmaxf(x, -50.0f), 50.0f); }

__device__ __forceinline__ uint32_t s2u(const void* p) {
    return (uint32_t)__cvta_generic_to_shared(p);
}
__device__ __forceinline__ void mbar_init(uint32_t mbar, uint32_t cnt) {
    asm volatile("mbarrier.init.shared.b64 [%0], %1;" :: "r"(mbar), "r"(cnt) : "memory");
}
__device__ __forceinline__ void mbar_expect_tx(uint32_t mbar, uint32_t bytes) {
    asm volatile("mbarrier.arrive.expect_tx.shared.b64 _, [%0], %1;" :: "r"(mbar), "r"(bytes) : "memory");
}
__device__ __forceinline__ void mbar_wait(uint32_t mbar, uint32_t parity) {
    asm volatile("{\n\t.reg .pred P1;\nLW%=:\n\t"
                 "mbarrier.try_wait.parity.shared::cta.b64 P1, [%0], %1;\n\t"
                 "@!P1 bra LW%=;\n}"
                 :: "r"(mbar), "r"(parity) : "memory");
}
__device__ __forceinline__ void bulk_cp(uint32_t dst, const void* src, uint32_t bytes, uint32_t mbar) {
    asm volatile("cp.async.bulk.shared::cluster.global.mbarrier::complete_tx::bytes [%0], [%1], %2, [%3];"
                 :: "r"(dst), "l"(src), "r"(bytes), "r"(mbar) : "memory");
}
__device__ __forceinline__ void cpasync16(uint32_t dst, const void* src) {
    asm volatile("cp.async.cg.shared.global [%0], [%1], 16;" :: "r"(dst), "l"(src));
}
__device__ __forceinline__ void cp_commit() { asm volatile("cp.async.commit_group;" ::: "memory"); }
__device__ __forceinline__ void cp_wait1() { asm volatile("cp.async.wait_group 1;" ::: "memory"); }

#define LDMX4(r0, r1, r2, r3, a) \
    asm volatile("ldmatrix.sync.aligned.m8n8.x4.shared.b16 {%0,%1,%2,%3}, [%4];" \
                 : "=r"(r0), "=r"(r1), "=r"(r2), "=r"(r3) : "r"(a))

__device__ __forceinline__ void mma16816(float* d, const uint32_t* a, const uint32_t* b) {
    asm volatile("mma.sync.aligned.m16n8k16.row.col.f32.f16.f16.f32 "
                 "{%0,%1,%2,%3}, {%4,%5,%6,%7}, {%8,%9}, {%0,%1,%2,%3};"
                 : "+f"(d[0]), "+f"(d[1]), "+f"(d[2]), "+f"(d[3])
                 : "r"(a[0]), "r"(a[1]), "r"(a[2]), "r"(a[3]), "r"(b[0]), "r"(b[1]));
}

// ================= init kernels =================
__global__ void init_pair(const float* __restrict__ dh, const float* __restrict__ dc) {
    int idx = blockIdx.x * blockDim.x + threadIdx.x;   // 32768
    int l = idx >> 13, rem = idx & 8191, b2 = rem >> 9, j = rem & 511;
    int b0 = 2 * b2, b1 = b0 + 1;
    g_hb[0][l][b2][j] = pk2(dh[(l * 32 + b0) * 512 + j], dh[(l * 32 + b1) * 512 + j]);
    g_c2[l][b2][j]    = pk2(dc[(l * 32 + b0) * 512 + j], dc[(l * 32 + b1) * 512 + j]);
}

__global__ void init_emb(const float* __restrict__ emb, const int* __restrict__ target) {
    int idx = blockIdx.x * blockDim.x + threadIdx.x;   // 51*8192
    if (idx >= NTT * 8192) return;
    int t = idx >> 13, rem = idx & 8191, b2 = rem >> 9, k = rem & 511;
    int b0 = 2 * b2, b1 = b0 + 1;
    int t0 = (t == 0) ? 0 : target[b0 * NTT + t - 1];
    int t1 = (t == 0) ? 0 : target[b1 * NTT + t - 1];
    g_emb2[t][b2][k] = pk2(emb[t0 * 512 + k], emb[t1 * 512 + k]);
}

// round W_out to fp16 once
__global__ void conv_w(const float* __restrict__ W) {
    int idx = blockIdx.x * blockDim.x + threadIdx.x;   // 32000*64
    if (idx >= NV * 64) return;
    size_t base = (size_t)idx * 8;
    const float4* s = (const float4*)(W + base);
    float4 a = s[0], b = s[1];
    float v[8] = {a.x, a.y, a.z, a.w, b.x, b.y, b.z, b.w};
    __align__(16) __half h[8];
    #pragma unroll
    for (int i = 0; i < 8; i++) h[i] = __float2half_rn(v[i]);
    *(uint4*)&g_Ws[base] = *(const uint4*)h;
}

// split htop into fp16 hi+lo
__global__ void conv_h() {
    int idx = blockIdx.x * blockDim.x + threadIdx.x;   // 1664*64
    if (idx >= 1664 * 64) return;
    size_t base = (size_t)idx * 8;
    const float4* s = (const float4*)(g_htop + base);
    float4 a = s[0], b = s[1];
    float v[8] = {a.x, a.y, a.z, a.w, b.x, b.y, b.z, b.w};
    __align__(16) __half hi[8], lo[8];
    #pragma unroll
    for (int i = 0; i < 8; i++) {
        hi[i] = __float2half_rn(v[i]);
        lo[i] = __float2half_rn(v[i] - __half2float(hi[i]));
    }
    *(uint4*)&g_Hs[0][base] = *(const uint4*)hi;
    *(uint4*)&g_Hs[1][base] = *(const uint4*)lo;
}

// ================= wavefront LSTM =================
// Per stage: 128 blocks (64 j-tiles x 2 batch-halves), 512 threads (16 warps).
// Warp = (khalf, gate, jsub): 4 rows x 8 batch-pairs, lane-split K by 32,
// weight prefetch depth 4 (16 outstanding LDGs per warp).
__global__ __launch_bounds__(512) void lstm_diag(
    int d,
    const float* __restrict__ Wih, const float* __restrict__ Whh,
    const float* __restrict__ bih, const float* __restrict__ bhh)
{
    extern __shared__ u64 sm_[];
    u64* xh2 = sm_;                        // [2 khalf][8 b2][512] u64 = 64KB
    u64* gates2 = sm_ + 8192;              // [2][4][8 r][8 b2] u64 = 4KB
    u64* mbar_st = sm_ + 8192 + 512;

    const int lmin = (d > NTT - 1) ? d - (NTT - 1) : 0;
    const int within = blockIdx.x & 127;
    const int l = lmin + (blockIdx.x >> 7);
    const int t = d - l;
    const int par = t & 1;
    const int bhalf = within >> 6;
    const int j0 = (within & 63) * 8;
    const int tid = threadIdx.x, lane = tid & 31, wid = tid >> 5;

    uint32_t mbar = s2u(mbar_st);
    if (tid == 0) mbar_init(mbar, 1);
    __syncthreads();
    if (tid == 0) {
        const u64* xsrc = ((l == 0) ? &g_emb2[t][0][0] : &g_x[par][l][0][0]) + bhalf * 4096;
        const u64* hsrc = &g_hb[par][l][0][0] + bhalf * 4096;
        mbar_expect_tx(mbar, 65536);
        bulk_cp(s2u(xh2), xsrc, 32768, mbar);
        bulk_cp(s2u(xh2 + 4096), hsrc, 32768, mbar);
    }

    // ---- warp decode + deep weight prefetch (independent of SMEM arrival) ----
    const int khalf = wid & 1;
    const int gate  = (wid >> 1) & 3;
    const int jsub  = wid >> 3;
    const float* wp = (khalf ? Whh : Wih)
        + ((size_t)(l * 2048 + gate * 512 + j0 + jsub * 4)) * 512 + lane;
    float wc[4][4];   // [pipeline stage][row]
    #pragma unroll
    for (int p = 0; p < 4; p++)
        #pragma unroll
        for (int r = 0; r < 4; r++) wc[p][r] = wp[r * 512 + p * 32];

    mbar_wait(mbar, 0);

    const u64* xb = xh2 + khalf * 4096 + lane;
    u64 acc[4][8];
    #pragma unroll
    for (int r = 0; r < 4; r++)
        #pragma unroll
        for (int b = 0; b < 8; b++) acc[r][b] = 0ULL;

    #pragma unroll
    for (int kc = 0; kc < 16; kc++) {
        const int sl = kc & 3;
        u64 aa[4];
        #pragma unroll
        for (int r = 0; r < 4; r++) aa[r] = pk2(wc[sl][r], wc[sl][r]);
        if (kc < 12) {
            #pragma unroll
            for (int r = 0; r < 4; r++) wc[sl][r] = wp[r * 512 + (kc + 4) * 32];
        }
        #pragma unroll
        for (int b = 0; b < 8; b++) {
            u64 xv = xb[b * 512 + kc * 32];
            #pragma unroll
            for (int r = 0; r < 4; r++) acc[r][b] = ffma2(aa[r], xv, acc[r][b]);
        }
    }

    #pragma unroll
    for (int off = 16; off > 0; off >>= 1) {
        #pragma unroll
        for (int r = 0; r < 4; r++)
            #pragma unroll
            for (int b = 0; b < 8; b++)
                acc[r][b] = fadd2(acc[r][b], __shfl_xor_sync(0xffffffffu, acc[r][b], off));
    }
    if (lane == 0) {
        #pragma unroll
        for (int r = 0; r < 4; r++)
            #pragma unroll
            for (int b = 0; b < 8; b++)
                gates2[((khalf * 4 + gate) * 8 + jsub * 4 + r) * 8 + b] = acc[r][b];
    }
    __syncthreads();

    // ---- pointwise epilogue: 8 j x 8 b2 = 64 threads ----
    if (tid < 64) {
        int jl = tid >> 3, b2l = tid & 7;
        int b2 = bhalf * 8 + b2l;
        int j = j0 + jl;
        float gv0[4], gv1[4];
        #pragma unroll
        for (int g = 0; g < 4; g++) {
            u64 s = fadd2(gates2[((0 * 4 + g) * 8 + jl) * 8 + b2l],
                          gates2[((1 * 4 + g) * 8 + jl) * 8 + b2l]);
            float lo, hi; upk2(s, lo, hi);
            float bb = bih[l * 2048 + g * 512 + j] + bhh[l * 2048 + g * 512 + j];
            gv0[g] = lo + bb; gv1[g] = hi + bb;
        }
        float c0, c1; upk2(g_c2[l][b2][j], c0, c1);

        float i0 = sigmoidf_(gv0[0]), f0 = sigmoidf_(gv0[1]);
        float gg0 = tanhf(gv0[2]),   o0 = sigmoidf_(gv0[3]);
        float cn0 = f0 * c0 + i0 * gg0;
        float h0 = o0 * tanhf(cn0);

        float i1 = sigmoidf_(gv1[0]), f1 = sigmoidf_(gv1[1]);
        float gg1 = tanhf(gv1[2]),   o1 = sigmoidf_(gv1[3]);
        float cn1 = f1 * c1 + i1 * gg1;
        float h1 = o1 * tanhf(cn1);

        if (l < 3) {
            g_x[par][l + 1][b2][j] = pk2(h0, h1);
        } else {
            int b0 = 2 * b2;
            g_htop[((size_t)t * 32 + b0) * 512 + j] = h0;
            g_htop[((size_t)t * 32 + b0 + 1) * 512 + j] = h1;
        }
        g_hb[par ^ 1][l][b2][j] = pk2(clip50(h0), clip50(h1));
        g_c2[l][b2][j] = pk2(clip50(cn0), clip50(cn1));
    }
}

// ================= mma.sync fp16 projection =================
// C[1664,32000] = (Ahi + Alo) @ W^T, 2 passes of K=512 each (16 chunks of 64).
// BM=BN=128, BK=64 (128B rows, XOR swizzle), 8 warps (4m x 2n), warp tile 32x64.
__global__ __launch_bounds__(256) void proj_mma(
    const float* __restrict__ bout, float* __restrict__ out)
{
    extern __shared__ __align__(16) unsigned char ps[];
    const uint32_t sb = s2u(ps);
    const int tid = threadIdx.x, lane = tid & 31, wid = tid >> 5;
    const int wm = wid & 3, wn = wid >> 2;
    const int bm = blockIdx.y * 128, bn = blockIdx.x * 128;

    const uint32_t Ab[2] = {sb, sb + 16384};
    const uint32_t Bb[2] = {sb + 32768, sb + 49152};

    float acc[2][8][4];
    #pragma unroll
    for (int f = 0; f < 2; f++)
        #pragma unroll
        for (int p = 0; p < 8; p++)
            #pragma unroll
            for (int q = 0; q < 4; q++) acc[f][p][q] = 0.0f;

    const int sr = tid >> 3, su = tid & 7;

    // prologue: chunk 0 (pass 0 = Ahi)
    #pragma unroll
    for (int i = 0; i < 4; i++) {
        int r = sr + i * 32;
        cpasync16(Ab[0] + r * 128 + ((su ^ (r & 7)) << 4),
                  g_Hs[0] + (size_t)(bm + r) * 512 + su * 8);
        cpasync16(Bb[0] + r * 128 + ((su ^ (r & 7)) << 4),
                  g_Ws + (size_t)(bn + r) * 512 + su * 8);
    }
    cp_commit();

    for (int c = 0; c < 16; c++) {
        if (c + 1 < 16) {
            int c2 = c + 1, pass = c2 >> 3, k0 = (c2 & 7) * 64;
            const __half* Ag = g_Hs[pass];
            uint32_t da = Ab[c2 & 1], db = Bb[c2 & 1];
            #pragma unroll
            for (int i = 0; i < 4; i++) {
                int r = sr + i * 32;
                cpasync16(da + r * 128 + ((su ^ (r & 7)) << 4),
                          Ag + (size_t)(bm + r) * 512 + k0 + su * 8);
                cpasync16(db + r * 128 + ((su ^ (r & 7)) << 4),
                          g_Ws + (size_t)(bn + r) * 512 + k0 + su * 8);
            }
        }
        cp_commit();
        cp_wait1();
        __syncthreads();

        const uint32_t Abase = Ab[c & 1], Bbase = Bb[c & 1];
        const int jA = lane >> 3;
        #pragma unroll
        for (int q = 0; q < 4; q++) {
            uint32_t a[2][4];
            #pragma unroll
            for (int f = 0; f < 2; f++) {
                int r = wm * 32 + f * 16 + (lane & 7) + ((jA & 1) << 3);
                int u = 2 * q + (jA >> 1);
                uint32_t ad = Abase + r * 128 + ((u ^ (r & 7)) << 4);
                LDMX4(a[f][0], a[f][1], a[f][2], a[f][3], ad);
            }
            uint32_t b[8][2];
            #pragma unroll
            for (int fp = 0; fp < 4; fp++) {
                int r = wn * 64 + fp * 16 + (lane & 7) + ((jA >> 1) << 3);
                int u = 2 * q + (jA & 1);
                uint32_t bd = Bbase + r * 128 + ((u ^ (r & 7)) << 4);
                LDMX4(b[2 * fp][0], b[2 * fp][1], b[2 * fp + 1][0], b[2 * fp + 1][1], bd);
            }
            #pragma unroll
            for (int f = 0; f < 2; f++)
                #pragma unroll
                for (int p = 0; p < 8; p++)
                    mma16816(acc[f][p], a[f], b[p]);
        }
        __syncthreads();
    }

    // epilogue: C[m][n] + bias, remap m=(t*32+b) -> out[b][t][:]
    #pragma unroll
    for (int f = 0; f < 2; f++) {
        int m0 = bm + wm * 32 + f * 16 + (lane >> 2);
        #pragma unroll
        for (int p = 0; p < 8; p++) {
            int n = bn + wn * 64 + p * 8 + 2 * (lane & 3);
            float2 bo = *(const float2*)&bout[n];
            int m = m0;
            if (m < 1632) {
                int tt = m >> 5, b = m & 31;
                float2 r0 = make_float2(acc[f][p][0] + bo.x, acc[f][p][1] + bo.y);
                *(float2*)&out[(size_t)b * NTT * NV + (size_t)tt * NV + n] = r0;
            }
            m = m0 + 8;
            if (m < 1632) {
                int tt = m >> 5, b = m & 31;
                float2 r1 = make_float2(acc[f][p][2] + bo.x, acc[f][p][3] + bo.y);
                *(float2*)&out[(size_t)b * NTT * NV + (size_t)tt * NV + n] = r1;
            }
        }
    }
}

// ================= final hidden state tail =================
__global__ void write_hfin(float* __restrict__ out) {
    int idx = blockIdx.x * blockDim.x + threadIdx.x;   // 65536
    int l = idx >> 14, b = (idx >> 9) & 31, j = idx & 511;
    float lo, hi; upk2(g_hb[1][l][b >> 1][j], lo, hi);
    out[(size_t)NB * NTT * NV + idx] = (b & 1) ? hi : lo;
}

extern "C" void kernel_launch(void* const* d_in, const int* in_sizes, int n_in,
                              void* d_out, int out_size)
{
    (void)in_sizes; (void)n_in; (void)out_size;
    const float* dh   = (const float*)d_in[1];
    const float* dc   = (const float*)d_in[2];
    const int*   tgt  = (const int*)  d_in[3];
    const float* emb  = (const float*)d_in[4];
    const float* Wih  = (const float*)d_in[5];
    const float* Whh  = (const float*)d_in[6];
    const float* bih  = (const float*)d_in[7];
    const float* bhh  = (const float*)d_in[8];
    const float* Wout = (const float*)d_in[9];
    const float* bout = (const float*)d_in[10];
    float* out = (float*)d_out;

    const int SMEM_LSTM = 8192 * 8 + 512 * 8 + 64;   // ~69.6KB
    const int SMEM_PROJ = 65536;
    cudaFuncSetAttribute(lstm_diag, cudaFuncAttributeMaxDynamicSharedMemorySize, SMEM_LSTM);
    cudaFuncSetAttribute(proj_mma, cudaFuncAttributeMaxDynamicSharedMemorySize, SMEM_PROJ);

    init_pair<<<128, 256>>>(dh, dc);
    init_emb<<<1632, 256>>>(emb, tgt);
    conv_w<<<8000, 256>>>(Wout);

    for (int d = 0; d < NTT + NL - 1; d++) {
        int lmin = (d > NTT - 1) ? d - (NTT - 1) : 0;
        int lmax = (d < NL - 1) ? d : NL - 1;
        int ns = lmax - lmin + 1;
        lstm_diag<<<128 * ns, 512, SMEM_LSTM>>>(d, Wih, Whh, bih, bhh);
    }

    conv_h<<<416, 256>>>();
    proj_mma<<<dim3(250, 13), 256, SMEM_PROJ>>>(bout, out);
    write_hfin<<<256, 256>>>(out);
}

// round 8
// speedup vs baseline: 1.1902x; 1.1902x over previous
#include <cuda_runtime.h>
#include <cuda_fp16.h>
#include <math.h>
#include <stdint.h>

#define NL 4
#define NB 32
#define NH 512
#define NV 32000
#define NTT 51

typedef unsigned long long u64;

// ================= persistent device scratch =================
__device__ u64 g_x[2][NL][16][512];      // layer-input pairs (l>=1), ping-pong by t parity
__device__ u64 g_hb[2][NL][16][512];     // clamped hidden pairs, ping-pong by t parity
__device__ u64 g_c2[NL][16][512];        // clamped cell pairs
__device__ u64 g_emb2[NTT][16][512];     // pre-gathered embedding pairs per timestep
__device__ float g_htop[1664 * NH];      // top-layer hidden per step (pad rows stay 0)

// fp16 operands for the projection (single pass)
__device__ __half g_Hs[1664 * 512];
__device__ __half g_Ws[NV * 512];

// ================= helpers =================
__device__ __forceinline__ u64 pk2(float lo, float hi) {
    u64 r;
    asm("mov.b64 %0, {%1, %2};" : "=l"(r) : "r"(__float_as_uint(lo)), "r"(__float_as_uint(hi)));
    return r;
}
__device__ __forceinline__ void upk2(u64 v, float &lo, float &hi) {
    unsigned a, b;
    asm("mov.b64 {%0, %1}, %2;" : "=r"(a), "=r"(b) : "l"(v));
    lo = __uint_as_float(a); hi = __uint_as_float(b);
}
__device__ __forceinline__ u64 ffma2(u64 a, u64 b, u64 c) {
    u64 d;
    asm("fma.rn.f32x2 %0, %1, %2, %3;" : "=l"(d) : "l"(a), "l"(b), "l"(c));
    return d;
}
__device__ __forceinline__ u64 fadd2(u64 a, u64 b) {
    u64 d;
    asm("add.rn.f32x2 %0, %1, %2;" : "=l"(d) : "l"(a), "l"(b));
    return d;
}
__device__ __forceinline__ float sigmoidf_(float x) { return 1.0f / (1.0f + expf(-x)); }
__device__ __forceinline__ float clip50(float x) { return fminf(fmaxf(x, -50.0f), 50.0f); }

__device__ __forceinline__ uint32_t s2u(const void* p) {
    return (uint32_t)__cvta_generic_to_shared(p);
}
__device__ __forceinline__ void cpasync16(uint32_t dst, const void* src) {
    asm volatile("cp.async.cg.shared.global [%0], [%1], 16;" :: "r"(dst), "l"(src));
}
__device__ __forceinline__ void cp_commit() { asm volatile("cp.async.commit_group;" ::: "memory"); }
__device__ __forceinline__ void cp_wait1() { asm volatile("cp.async.wait_group 1;" ::: "memory"); }

#define LDMX4(r0, r1, r2, r3, a) \
    asm volatile("ldmatrix.sync.aligned.m8n8.x4.shared.b16 {%0,%1,%2,%3}, [%4];" \
                 : "=r"(r0), "=r"(r1), "=r"(r2), "=r"(r3) : "r"(a))

__device__ __forceinline__ void mma16816(float* d, const uint32_t* a, const uint32_t* b) {
    asm volatile("mma.sync.aligned.m16n8k16.row.col.f32.f16.f16.f32 "
                 "{%0,%1,%2,%3}, {%4,%5,%6,%7}, {%8,%9}, {%0,%1,%2,%3};"
                 : "+f"(d[0]), "+f"(d[1]), "+f"(d[2]), "+f"(d[3])
                 : "r"(a[0]), "r"(a[1]), "r"(a[2]), "r"(a[3]), "r"(b[0]), "r"(b[1]));
}

// ================= init kernels =================
__global__ void init_pair(const float* __restrict__ dh, const float* __restrict__ dc) {
    int idx = blockIdx.x * blockDim.x + threadIdx.x;   // 32768
    int l = idx >> 13, rem = idx & 8191, b2 = rem >> 9, j = rem & 511;
    int b0 = 2 * b2, b1 = b0 + 1;
    g_hb[0][l][b2][j] = pk2(dh[(l * 32 + b0) * 512 + j], dh[(l * 32 + b1) * 512 + j]);
    g_c2[l][b2][j]    = pk2(dc[(l * 32 + b0) * 512 + j], dc[(l * 32 + b1) * 512 + j]);
}

__global__ void init_emb(const float* __restrict__ emb, const int* __restrict__ target) {
    int idx = blockIdx.x * blockDim.x + threadIdx.x;   // 51*8192
    if (idx >= NTT * 8192) return;
    int t = idx >> 13, rem = idx & 8191, b2 = rem >> 9, k = rem & 511;
    int b0 = 2 * b2, b1 = b0 + 1;
    int t0 = (t == 0) ? 0 : target[b0 * NTT + t - 1];
    int t1 = (t == 0) ? 0 : target[b1 * NTT + t - 1];
    g_emb2[t][b2][k] = pk2(emb[t0 * 512 + k], emb[t1 * 512 + k]);
}

// round W_out to fp16 once
__global__ void conv_w(const float* __restrict__ W) {
    int idx = blockIdx.x * blockDim.x + threadIdx.x;   // 32000*64
    if (idx >= NV * 64) return;
    size_t base = (size_t)idx * 8;
    const float4* s = (const float4*)(W + base);
    float4 a = s[0], b = s[1];
    float v[8] = {a.x, a.y, a.z, a.w, b.x, b.y, b.z, b.w};
    __align__(16) __half h[8];
    #pragma unroll
    for (int i = 0; i < 8; i++) h[i] = __float2half_rn(v[i]);
    *(uint4*)&g_Ws[base] = *(const uint4*)h;
}

// round htop to fp16
__global__ void conv_h() {
    int idx = blockIdx.x * blockDim.x + threadIdx.x;   // 1664*64
    if (idx >= 1664 * 64) return;
    size_t base = (size_t)idx * 8;
    const float4* s = (const float4*)(g_htop + base);
    float4 a = s[0], b = s[1];
    float v[8] = {a.x, a.y, a.z, a.w, b.x, b.y, b.z, b.w};
    __align__(16) __half h[8];
    #pragma unroll
    for (int i = 0; i < 8; i++) h[i] = __float2half_rn(v[i]);
    *(uint4*)&g_Hs[base] = *(const uint4*)h;
}

// ================= wavefront LSTM =================
// Per stage: 256 blocks (128 j-tiles x 2 batch-halves), 256 threads (8 warps).
// No SMEM staging: x/h read straight from global through L1 (64KB slab, 8x reuse).
// Warp = (khalf, gate): 4 rows x 8 batch-pairs, lane-split K by 32,
// weight prefetch depth 4, x prefetch depth 1.
__global__ __launch_bounds__(256, 2) void lstm_diag(
    int d,
    const float* __restrict__ Wih, const float* __restrict__ Whh,
    const float* __restrict__ bih, const float* __restrict__ bhh)
{
    __shared__ u64 gates2[2 * 4 * 4 * 8];   // [khalf][gate][r][b2l] = 2KB

    const int lmin = (d > NTT - 1) ? d - (NTT - 1) : 0;
    const int within = blockIdx.x & 255;
    const int l = lmin + (blockIdx.x >> 8);
    const int t = d - l;
    const int par = t & 1;
    const int bhalf = within >> 7;
    const int j0 = (within & 127) * 4;
    const int tid = threadIdx.x, lane = tid & 31, wid = tid >> 5;

    const int khalf = wid & 1;
    const int gate  = (wid >> 1) & 3;

    const u64* xsrc = ((l == 0) ? &g_emb2[t][0][0] : &g_x[par][l][0][0]) + bhalf * 4096;
    const u64* hsrc = &g_hb[par][l][0][0] + bhalf * 4096;
    const u64* src  = (khalf ? hsrc : xsrc) + lane;

    const float* wp = (khalf ? Whh : Wih)
        + ((size_t)(l * 2048 + gate * 512 + j0)) * 512 + lane;

    // deep prefetch: 4 k-chunks of weights + 1 k-chunk of activations
    float wc[4][4];
    #pragma unroll
    for (int p = 0; p < 4; p++)
        #pragma unroll
        for (int r = 0; r < 4; r++) wc[p][r] = wp[r * 512 + p * 32];

    u64 xv[8];
    #pragma unroll
    for (int b = 0; b < 8; b++) xv[b] = src[b * 512];

    u64 acc[4][8];
    #pragma unroll
    for (int r = 0; r < 4; r++)
        #pragma unroll
        for (int b = 0; b < 8; b++) acc[r][b] = 0ULL;

    #pragma unroll
    for (int kc = 0; kc < 16; kc++) {
        const int sl = kc & 3;
        u64 aa[4];
        #pragma unroll
        for (int r = 0; r < 4; r++) aa[r] = pk2(wc[sl][r], wc[sl][r]);
        if (kc < 12) {
            #pragma unroll
            for (int r = 0; r < 4; r++) wc[sl][r] = wp[r * 512 + (kc + 4) * 32];
        }
        u64 xn[8];
        if (kc < 15) {
            #pragma unroll
            for (int b = 0; b < 8; b++) xn[b] = src[b * 512 + (kc + 1) * 32];
        }
        #pragma unroll
        for (int b = 0; b < 8; b++) {
            #pragma unroll
            for (int r = 0; r < 4; r++) acc[r][b] = ffma2(aa[r], xv[b], acc[r][b]);
        }
        if (kc < 15) {
            #pragma unroll
            for (int b = 0; b < 8; b++) xv[b] = xn[b];
        }
    }

    #pragma unroll
    for (int off = 16; off > 0; off >>= 1) {
        #pragma unroll
        for (int r = 0; r < 4; r++)
            #pragma unroll
            for (int b = 0; b < 8; b++)
                acc[r][b] = fadd2(acc[r][b], __shfl_xor_sync(0xffffffffu, acc[r][b], off));
    }
    if (lane == 0) {
        #pragma unroll
        for (int r = 0; r < 4; r++)
            #pragma unroll
            for (int b = 0; b < 8; b++)
                gates2[(((khalf * 4 + gate) * 4) + r) * 8 + b] = acc[r][b];
    }
    __syncthreads();

    // ---- pointwise epilogue: 4 j x 8 b2 = 32 threads ----
    if (tid < 32) {
        int jl = tid >> 3, b2l = tid & 7;
        int b2 = bhalf * 8 + b2l;
        int j = j0 + jl;
        float gv0[4], gv1[4];
        #pragma unroll
        for (int g = 0; g < 4; g++) {
            u64 s = fadd2(gates2[((0 * 4 + g) * 4 + jl) * 8 + b2l],
                          gates2[((1 * 4 + g) * 4 + jl) * 8 + b2l]);
            float lo, hi; upk2(s, lo, hi);
            float bb = bih[l * 2048 + g * 512 + j] + bhh[l * 2048 + g * 512 + j];
            gv0[g] = lo + bb; gv1[g] = hi + bb;
        }
        float c0, c1; upk2(g_c2[l][b2][j], c0, c1);

        float i0 = sigmoidf_(gv0[0]), f0 = sigmoidf_(gv0[1]);
        float gg0 = tanhf(gv0[2]),   o0 = sigmoidf_(gv0[3]);
        float cn0 = f0 * c0 + i0 * gg0;
        float h0 = o0 * tanhf(cn0);

        float i1 = sigmoidf_(gv1[0]), f1 = sigmoidf_(gv1[1]);
        float gg1 = tanhf(gv1[2]),   o1 = sigmoidf_(gv1[3]);
        float cn1 = f1 * c1 + i1 * gg1;
        float h1 = o1 * tanhf(cn1);

        if (l < 3) {
            g_x[par][l + 1][b2][j] = pk2(h0, h1);
        } else {
            int b0 = 2 * b2;
            g_htop[((size_t)t * 32 + b0) * 512 + j] = h0;
            g_htop[((size_t)t * 32 + b0 + 1) * 512 + j] = h1;
        }
        g_hb[par ^ 1][l][b2][j] = pk2(clip50(h0), clip50(h1));
        g_c2[l][b2][j] = pk2(clip50(cn0), clip50(cn1));
    }
}

// ================= mma.sync fp16 projection (single pass) =================
// C[1664,32000] = A @ W^T, K=512 (8 chunks of 64).
// BM=BN=128, BK=64 (128B rows, XOR swizzle), 8 warps (4m x 2n), warp tile 32x64.
__global__ __launch_bounds__(256) void proj_mma(
    const float* __restrict__ bout, float* __restrict__ out)
{
    extern __shared__ __align__(16) unsigned char ps[];
    const uint32_t sb = s2u(ps);
    const int tid = threadIdx.x, lane = tid & 31, wid = tid >> 5;
    const int wm = wid & 3, wn = wid >> 2;
    const int bm = blockIdx.y * 128, bn = blockIdx.x * 128;

    const uint32_t Ab[2] = {sb, sb + 16384};
    const uint32_t Bb[2] = {sb + 32768, sb + 49152};

    float acc[2][8][4];
    #pragma unroll
    for (int f = 0; f < 2; f++)
        #pragma unroll
        for (int p = 0; p < 8; p++)
            #pragma unroll
            for (int q = 0; q < 4; q++) acc[f][p][q] = 0.0f;

    const int sr = tid >> 3, su = tid & 7;

    // prologue: chunk 0
    #pragma unroll
    for (int i = 0; i < 4; i++) {
        int r = sr + i * 32;
        cpasync16(Ab[0] + r * 128 + ((su ^ (r & 7)) << 4),
                  g_Hs + (size_t)(bm + r) * 512 + su * 8);
        cpasync16(Bb[0] + r * 128 + ((su ^ (r & 7)) << 4),
                  g_Ws + (size_t)(bn + r) * 512 + su * 8);
    }
    cp_commit();

    for (int c = 0; c < 8; c++) {
        if (c + 1 < 8) {
            int k0 = (c + 1) * 64;
            uint32_t da = Ab[(c + 1) & 1], db = Bb[(c + 1) & 1];
            #pragma unroll
            for (int i = 0; i < 4; i++) {
                int r = sr + i * 32;
                cpasync16(da + r * 128 + ((su ^ (r & 7)) << 4),
                          g_Hs + (size_t)(bm + r) * 512 + k0 + su * 8);
                cpasync16(db + r * 128 + ((su ^ (r & 7)) << 4),
                          g_Ws + (size_t)(bn + r) * 512 + k0 + su * 8);
            }
        }
        cp_commit();
        cp_wait1();
        __syncthreads();

        const uint32_t Abase = Ab[c & 1], Bbase = Bb[c & 1];
        const int jA = lane >> 3;
        #pragma unroll
        for (int q = 0; q < 4; q++) {
            uint32_t a[2][4];
            #pragma unroll
            for (int f = 0; f < 2; f++) {
                int r = wm * 32 + f * 16 + (lane & 7) + ((jA & 1) << 3);
                int u = 2 * q + (jA >> 1);
                uint32_t ad = Abase + r * 128 + ((u ^ (r & 7)) << 4);
                LDMX4(a[f][0], a[f][1], a[f][2], a[f][3], ad);
            }
            uint32_t b[8][2];
            #pragma unroll
            for (int fp = 0; fp < 4; fp++) {
                int r = wn * 64 + fp * 16 + (lane & 7) + ((jA >> 1) << 3);
                int u = 2 * q + (jA & 1);
                uint32_t bd = Bbase + r * 128 + ((u ^ (r & 7)) << 4);
                LDMX4(b[2 * fp][0], b[2 * fp][1], b[2 * fp + 1][0], b[2 * fp + 1][1], bd);
            }
            #pragma unroll
            for (int f = 0; f < 2; f++)
                #pragma unroll
                for (int p = 0; p < 8; p++)
                    mma16816(acc[f][p], a[f], b[p]);
        }
        __syncthreads();
    }

    // epilogue: C[m][n] + bias, remap m=(t*32+b) -> out[b][t][:]
    #pragma unroll
    for (int f = 0; f < 2; f++) {
        int m0 = bm + wm * 32 + f * 16 + (lane >> 2);
        #pragma unroll
        for (int p = 0; p < 8; p++) {
            int n = bn + wn * 64 + p * 8 + 2 * (lane & 3);
            float2 bo = *(const float2*)&bout[n];
            int m = m0;
            if (m < 1632) {
                int tt = m >> 5, b = m & 31;
                float2 r0 = make_float2(acc[f][p][0] + bo.x, acc[f][p][1] + bo.y);
                *(float2*)&out[(size_t)b * NTT * NV + (size_t)tt * NV + n] = r0;
            }
            m = m0 + 8;
            if (m < 1632) {
                int tt = m >> 5, b = m & 31;
                float2 r1 = make_float2(acc[f][p][2] + bo.x, acc[f][p][3] + bo.y);
                *(float2*)&out[(size_t)b * NTT * NV + (size_t)tt * NV + n] = r1;
            }
        }
    }
}

// ================= final hidden state tail =================
__global__ void write_hfin(float* __restrict__ out) {
    int idx = blockIdx.x * blockDim.x + threadIdx.x;   // 65536
    int l = idx >> 14, b = (idx >> 9) & 31, j = idx & 511;
    float lo, hi; upk2(g_hb[1][l][b >> 1][j], lo, hi);
    out[(size_t)NB * NTT * NV + idx] = (b & 1) ? hi : lo;
}

extern "C" void kernel_launch(void* const* d_in, const int* in_sizes, int n_in,
                              void* d_out, int out_size)
{
    (void)in_sizes; (void)n_in; (void)out_size;
    const float* dh   = (const float*)d_in[1];
    const float* dc   = (const float*)d_in[2];
    const int*   tgt  = (const int*)  d_in[3];
    const float* emb  = (const float*)d_in[4];
    const float* Wih  = (const float*)d_in[5];
    const float* Whh  = (const float*)d_in[6];
    const float* bih  = (const float*)d_in[7];
    const float* bhh  = (const float*)d_in[8];
    const float* Wout = (const float*)d_in[9];
    const float* bout = (const float*)d_in[10];
    float* out = (float*)d_out;

    const int SMEM_PROJ = 65536;
    cudaFuncSetAttribute(proj_mma, cudaFuncAttributeMaxDynamicSharedMemorySize, SMEM_PROJ);

    init_pair<<<128, 256>>>(dh, dc);
    init_emb<<<1632, 256>>>(emb, tgt);
    conv_w<<<8000, 256>>>(Wout);

    for (int d = 0; d < NTT + NL - 1; d++) {
        int lmin = (d > NTT - 1) ? d - (NTT - 1) : 0;
        int lmax = (d < NL - 1) ? d : NL - 1;
        int ns = lmax - lmin + 1;
        lstm_diag<<<256 * ns, 256>>>(d, Wih, Whh, bih, bhh);
    }

    conv_h<<<416, 256>>>();
    proj_mma<<<dim3(250, 13), 256, SMEM_PROJ>>>(bout, out);
    write_hfin<<<256, 256>>>(out);
}